// round 11
// baseline (speedup 1.0000x reference)
#include <cuda_runtime.h>
#include <cuda_fp16.h>
#include <cuda_bf16.h>
#include <cstdint>

#define Nn   32
#define CIN  64
#define COUT 128
#define Vv   25
#define Tlen 300
#define Ss   3
#define VT   7500
#define VV   625
#define EPSf 1e-5f

typedef unsigned long long u64;

// ---- device scratch (allocation-free) ----
__device__ __align__(16) __half g_feat[Ss * Nn * COUT * VT]; // [s][n][o][w*300+t] (184.3 MB)
__device__ __align__(16) float  g_A[Ss * Nn * COUT * VV];    // [s][n][o][v*25+w]  (30.7 MB)
__device__ __align__(16) __half g_Xhi[Nn * CIN * VT];        // fp16 hi of x (30.7 MB)
__device__ __align__(16) __half g_Xlo[Nn * CIN * VT];        // fp16 lo of x (30.7 MB)
__device__ __align__(16) __half g_Whi[512 * 64];
__device__ __align__(16) __half g_Wlo[512 * 64];
__device__ __align__(16) float g_bias[512];

// ---- scalar/FMA2 helpers ----
__device__ __forceinline__ void fma2(u64& d, u64 a, u64 b) {
    asm("fma.rn.f32x2 %0, %1, %2, %0;" : "+l"(d) : "l"(a), "l"(b));
}
__device__ __forceinline__ u64 dup2(float v) {
    u64 r; asm("mov.b64 %0, {%1, %1};" : "=l"(r) : "f"(v)); return r;
}
__device__ __forceinline__ u64 pack2(float lo, float hi) {
    u64 r; asm("mov.b64 %0, {%1, %2};" : "=l"(r) : "f"(lo), "f"(hi)); return r;
}
__device__ __forceinline__ float lo32(u64 v) { return __uint_as_float((unsigned)v); }
__device__ __forceinline__ float hi32(u64 v) { return __uint_as_float((unsigned)(v >> 32)); }

__device__ __forceinline__ uint32_t smem_u32(const void* p) {
    uint32_t a;
    asm("{ .reg .u64 t; cvta.to.shared.u64 t, %1; cvt.u32.u64 %0, t; }" : "=r"(a) : "l"(p));
    return a;
}

// ---- mma.sync / ldmatrix (sm_80+, no arch-'a' gating) ----
#define LDSM_X4(r, addr) \
    asm volatile("ldmatrix.sync.aligned.m8n8.x4.shared.b16 {%0,%1,%2,%3}, [%4];" \
        : "=r"((r)[0]), "=r"((r)[1]), "=r"((r)[2]), "=r"((r)[3]) : "r"(addr))
#define LDSM_X4T(r, addr) \
    asm volatile("ldmatrix.sync.aligned.m8n8.x4.trans.shared.b16 {%0,%1,%2,%3}, [%4];" \
        : "=r"((r)[0]), "=r"((r)[1]), "=r"((r)[2]), "=r"((r)[3]) : "r"(addr))
#define LDSM_X2T(r, addr) \
    asm volatile("ldmatrix.sync.aligned.m8n8.x2.trans.shared.b16 {%0,%1}, [%2];" \
        : "=r"((r)[0]), "=r"((r)[1]) : "r"(addr))
#define MMA_F16(d, a, b) \
    asm volatile("mma.sync.aligned.m16n8k16.row.col.f32.f16.f16.f32 " \
        "{%0,%1,%2,%3}, {%4,%5,%6,%7}, {%8,%9}, {%0,%1,%2,%3};" \
        : "+f"((d)[0]), "+f"((d)[1]), "+f"((d)[2]), "+f"((d)[3]) \
        : "r"((a)[0]), "r"((a)[1]), "r"((a)[2]), "r"((a)[3]), "r"((b)[0]), "r"((b)[1]))

// ---------------------------------------------------------------------------
// kX: pre-split x (fp32) into fp16 hi/lo, linear layout identical to x.
// ---------------------------------------------------------------------------
__global__ void kX(const float* __restrict__ x) {
    size_t i4 = ((size_t)blockIdx.x * blockDim.x + threadIdx.x) * 4;
    if (i4 >= (size_t)Nn * CIN * VT) return;
    float4 v = *(const float4*)(x + i4);
    __half h0 = __float2half_rn(v.x), h1 = __float2half_rn(v.y);
    __half h2 = __float2half_rn(v.z), h3 = __float2half_rn(v.w);
    __half2 p0(h0, h1), p1(h2, h3);
    uint2 ph; ph.x = *(unsigned*)&p0; ph.y = *(unsigned*)&p1;
    *(uint2*)(g_Xhi + i4) = ph;
    __half2 q0(__float2half_rn(v.x - __half2float(h0)), __float2half_rn(v.y - __half2float(h1)));
    __half2 q1(__float2half_rn(v.z - __half2float(h2)), __float2half_rn(v.w - __half2float(h3)));
    uint2 pl; pl.x = *(unsigned*)&q0; pl.y = *(unsigned*)&q1;
    *(uint2*)(g_Xlo + i4) = pl;
}

// ---------------------------------------------------------------------------
// kW: split folded W into fp16 hi/lo + bias
// ---------------------------------------------------------------------------
__global__ void kW(const float* __restrict__ conv3_w, const float* __restrict__ conv3_b,
                   const float* __restrict__ down_w,  const float* __restrict__ down_b,
                   const float* __restrict__ dg, const float* __restrict__ dbeta,
                   const float* __restrict__ dm, const float* __restrict__ dvar) {
    int idx = blockIdx.x * blockDim.x + threadIdx.x;
    if (idx >= 512 * 64) return;
    int r = idx >> 6, k = idx & 63;
    float w;
    if (r < Ss * COUT) {
        w = conv3_w[r * CIN + k];
    } else {
        int o = r - Ss * COUT;
        w = dg[o] * rsqrtf(dvar[o] + EPSf) * down_w[o * CIN + k];
    }
    __half hi = __float2half_rn(w);
    g_Whi[idx] = hi;
    g_Wlo[idx] = __float2half_rn(w - __half2float(hi));
    if (k == 0) {
        float b;
        if (r < Ss * COUT) b = conv3_b[r];
        else {
            int o = r - Ss * COUT;
            float sc = dg[o] * rsqrtf(dvar[o] + EPSf);
            b = sc * (down_b[o] - dm[o]) + dbeta[o];
        }
        g_bias[r] = b;
    }
}

// ---------------------------------------------------------------------------
// kA: g_A = (ada_w . ada_A + ada_b) * PA. grid (20, n, s), 128 threads, FMA2.
// ---------------------------------------------------------------------------
#define KA_SMEM (64 * 16 * 8 + 64 * 125 * 4 + 32 * 4)
__global__ void __launch_bounds__(128)
kA(const float* __restrict__ adaA, const float* __restrict__ PA,
   const float* __restrict__ ada_w, const float* __restrict__ ada_b) {
    extern __shared__ char smA[];
    u64*   Wp  = (u64*)smA;
    float* Xa  = (float*)(smA + 64 * 16 * 8);
    float* bsm = (float*)(smA + 64 * 16 * 8 + 64 * 125 * 4);

    int tid = threadIdx.x;
    int s = blockIdx.z, n = blockIdx.y;
    int g = blockIdx.x & 3;
    int vw0 = (blockIdx.x >> 2) * 125;

    const float* wsrc = ada_w + s * COUT * CIN + g * 32 * CIN;
    for (int idx = tid; idx < 64 * 16; idx += 128) {
        int i = idx >> 4, op = idx & 15;
        Wp[i * 16 + op] = pack2(wsrc[(2 * op) * CIN + i], wsrc[(2 * op + 1) * CIN + i]);
    }
    for (int idx = tid; idx < 64 * 125; idx += 128) {
        int i = idx / 125, j = idx % 125;
        Xa[i * 125 + j] = adaA[(size_t)(n * CIN + i) * VV + vw0 + j];
    }
    if (tid < 32) bsm[tid] = ada_b[s * COUT + g * 32 + tid];
    __syncthreads();
    if (tid >= 125) return;

    int vw = vw0 + tid;
    float pa = PA[s * VV + vw];

    u64 acc[16];
#pragma unroll
    for (int p = 0; p < 16; p++) acc[p] = 0ull;

#pragma unroll 8
    for (int i = 0; i < CIN; i++) {
        u64 f2 = dup2(Xa[i * 125 + tid]);
        const ulonglong2* wr = (const ulonglong2*)(Wp + i * 16);
#pragma unroll
        for (int p = 0; p < 8; p++) {
            ulonglong2 wv = wr[p];
            fma2(acc[2 * p],     wv.x, f2);
            fma2(acc[2 * p + 1], wv.y, f2);
        }
    }
    float* outp = g_A + ((size_t)((s * Nn + n) * COUT) + g * 32) * VV + vw;
#pragma unroll
    for (int p = 0; p < 16; p++) {
        outp[(size_t)(2 * p) * VV]     = (lo32(acc[p]) + bsm[2 * p])     * pa;
        outp[(size_t)(2 * p + 1) * VV] = (hi32(acc[p]) + bsm[2 * p + 1]) * pa;
    }
}

// ---------------------------------------------------------------------------
// kB_m: tensor GEMM C[128r x 128c] = W[128x64] @ X[64 x 128c].
// 512 threads, 16 warps 4M x 4N, warp tile 32x32. B frags via ldmatrix.x4.trans
// (2 LDSM cover 4 n-groups). rg<3: 1 term -> g_feat; rg==3: 3 terms -> d_out.
// grid (59, 4, 32).
// ---------------------------------------------------------------------------
#define PADK 72
#define PADC 136
#define WHI_OFF 0
#define WLO_OFF (128 * PADK * 2)                // 18432
#define XHI_OFF (WLO_OFF + 128 * PADK * 2)      // 36864
#define XLO_OFF (XHI_OFF + 64 * PADC * 2)       // 54272
#define BIAS_OFF (XLO_OFF + 64 * PADC * 2)      // 71680
#define KBM_SMEM (BIAS_OFF + 128 * 4)           // 72192
__global__ void __launch_bounds__(512, 2)
kB_m(float* __restrict__ out) {
    extern __shared__ char sm[];
    __half* Whi_s = (__half*)(sm + WHI_OFF);
    __half* Wlo_s = (__half*)(sm + WLO_OFF);
    __half* Xhi_s = (__half*)(sm + XHI_OFF);
    __half* Xlo_s = (__half*)(sm + XLO_OFF);
    float* bias_s = (float*)(sm + BIAS_OFF);
    float* Cs = (float*)sm;   // reuse after mainloop: [128][132]

    int tid = threadIdx.x;
    int wid = tid >> 5, lane = tid & 31;
    int n = blockIdx.z, rg = blockIdx.y;
    int c0 = blockIdx.x * 128;
    int r0 = rg * 128;
    int ncols = VT - c0; if (ncols > 128) ncols = 128;   // 128 or 76 (mult of 4)
    bool isRes = (rg == 3);

    // ---- stage W hi (and lo only for residual rg) ----
    for (int idx = tid; idx < 1024; idx += 512) {
        int row = idx >> 3, kc = (idx & 7) * 8;
        uint4 v = *(const uint4*)(g_Whi + (size_t)(r0 + row) * 64 + kc);
        *(uint4*)(Whi_s + row * PADK + kc) = v;
    }
    if (isRes) {
        for (int idx = tid; idx < 1024; idx += 512) {
            int row = idx >> 3, kc = (idx & 7) * 8;
            uint4 v = *(const uint4*)(g_Wlo + (size_t)(r0 + row) * 64 + kc);
            *(uint4*)(Wlo_s + row * PADK + kc) = v;
        }
    }
    if (tid < 128) bias_s[tid] = g_bias[r0 + tid];

    // ---- stage X [k][c] fp16 straight copy (uint2) ----
    for (int idx = tid; idx < 64 * 32; idx += 512) {
        int k = idx >> 5, c4 = (idx & 31) << 2;
        uint2 v = make_uint2(0u, 0u);
        if (c4 < ncols) v = *(const uint2*)(g_Xhi + (size_t)(n * CIN + k) * VT + c0 + c4);
        *(uint2*)(Xhi_s + k * PADC + c4) = v;
        if (isRes) {
            uint2 vl = make_uint2(0u, 0u);
            if (c4 < ncols) vl = *(const uint2*)(g_Xlo + (size_t)(n * CIN + k) * VT + c0 + c4);
            *(uint2*)(Xlo_s + k * PADC + c4) = vl;
        }
    }
    __syncthreads();

    int wm0 = (wid & 3) * 32;          // 4 M groups of 32
    int wn0 = (wid >> 2) * 32;         // 4 N groups of 32
    uint32_t sbase = smem_u32(sm);

    float acc[2][4][4];
#pragma unroll
    for (int mi = 0; mi < 2; mi++)
#pragma unroll
        for (int ni = 0; ni < 4; ni++)
#pragma unroll
            for (int q = 0; q < 4; q++) acc[mi][ni][q] = 0.f;

#pragma unroll
    for (int k0 = 0; k0 < 64; k0 += 16) {
        int krow = k0 + (lane & 15);
        int ncl = ((lane >> 4) << 3);
        uint32_t a_hi[2][4], b_hi[4][2];
#pragma unroll
        for (int mi = 0; mi < 2; mi++) {
            int row = wm0 + mi * 16 + (lane & 15);
            int col = k0 + (lane >> 4) * 8;
            LDSM_X4(a_hi[mi], sbase + WHI_OFF + (uint32_t)(row * PADK + col) * 2);
        }
        {
            uint32_t r4[4];
            LDSM_X4T(r4, sbase + XHI_OFF + (uint32_t)(krow * PADC + wn0 + ncl) * 2);
            b_hi[0][0] = r4[0]; b_hi[0][1] = r4[1]; b_hi[1][0] = r4[2]; b_hi[1][1] = r4[3];
            LDSM_X4T(r4, sbase + XHI_OFF + (uint32_t)(krow * PADC + wn0 + 16 + ncl) * 2);
            b_hi[2][0] = r4[0]; b_hi[2][1] = r4[1]; b_hi[3][0] = r4[2]; b_hi[3][1] = r4[3];
        }
#pragma unroll
        for (int mi = 0; mi < 2; mi++)
#pragma unroll
            for (int ni = 0; ni < 4; ni++)
                MMA_F16(acc[mi][ni], a_hi[mi], b_hi[ni]);

        if (isRes) {
            uint32_t a_lo[2][4], b_lo[4][2];
#pragma unroll
            for (int mi = 0; mi < 2; mi++) {
                int row = wm0 + mi * 16 + (lane & 15);
                int col = k0 + (lane >> 4) * 8;
                LDSM_X4(a_lo[mi], sbase + WLO_OFF + (uint32_t)(row * PADK + col) * 2);
            }
            {
                uint32_t r4[4];
                LDSM_X4T(r4, sbase + XLO_OFF + (uint32_t)(krow * PADC + wn0 + ncl) * 2);
                b_lo[0][0] = r4[0]; b_lo[0][1] = r4[1]; b_lo[1][0] = r4[2]; b_lo[1][1] = r4[3];
                LDSM_X4T(r4, sbase + XLO_OFF + (uint32_t)(krow * PADC + wn0 + 16 + ncl) * 2);
                b_lo[2][0] = r4[0]; b_lo[2][1] = r4[1]; b_lo[3][0] = r4[2]; b_lo[3][1] = r4[3];
            }
#pragma unroll
            for (int mi = 0; mi < 2; mi++)
#pragma unroll
                for (int ni = 0; ni < 4; ni++) {
                    MMA_F16(acc[mi][ni], a_hi[mi], b_lo[ni]);
                    MMA_F16(acc[mi][ni], a_lo[mi], b_hi[ni]);
                }
        }
    }

    __syncthreads();

#pragma unroll
    for (int mi = 0; mi < 2; mi++)
#pragma unroll
        for (int ni = 0; ni < 4; ni++) {
            int r = wm0 + mi * 16 + (lane >> 2);
            int c = wn0 + ni * 8 + (lane & 3) * 2;
            *(float2*)(Cs + r * 132 + c)       = make_float2(acc[mi][ni][0], acc[mi][ni][1]);
            *(float2*)(Cs + (r + 8) * 132 + c) = make_float2(acc[mi][ni][2], acc[mi][ni][3]);
        }
    __syncthreads();

    for (int idx = tid; idx < 128 * 32; idx += 512) {
        int row = idx >> 5, c = (idx & 31) * 4;
        if (c >= ncols) continue;
        float4 v = *(float4*)(Cs + row * 132 + c);
        float b = bias_s[row];
        v.x += b; v.y += b; v.z += b; v.w += b;
        if (!isRes) {
            __half2 h0 = __floats2half2_rn(v.x, v.y);
            __half2 h1 = __floats2half2_rn(v.z, v.w);
            uint2 pk; pk.x = *(unsigned*)&h0; pk.y = *(unsigned*)&h1;
            *(uint2*)(g_feat + (size_t)((rg * Nn + n) * COUT + row) * VT + c0 + c) = pk;
        } else {
            *(float4*)(out + (size_t)(n * COUT + row) * VT + c0 + c) = v;
        }
    }
}

// ---------------------------------------------------------------------------
// kC_m: per (o, n): Out[25 x 300] = A[25 x 75] @ feat[75 x 300] (fp16 mma),
// then bn + residual(read from out) + relu. 256 threads (8 warps x 40 cols).
// Staging de-ALU'd (warp-per-row, incremental s/w); B frags 2x X4T + 1x X2T.
// ---------------------------------------------------------------------------
#define FS  312
#define CSd 308
#define KCM_A   (80 * FS * 2)          // 49920
#define KCM_SMEM (KCM_A + 32 * 80 * 2) // 55040
__global__ void __launch_bounds__(256)
kC_m(const float* __restrict__ bn_g, const float* __restrict__ bn_b,
     const float* __restrict__ bn_m, const float* __restrict__ bn_v,
     float* __restrict__ out) {
    extern __shared__ char sm[];
    __half* feat_s = (__half*)sm;           // [k=sw 80][t FS]
    __half* A_s    = (__half*)(sm + KCM_A); // [v 32][k 80]
    float*  Cs     = (float*)sm;            // reuse: [32][CSd]

    int tid = threadIdx.x;
    int wid = tid >> 5, lane = tid & 31;
    int o = blockIdx.x, n = blockIdx.y;

    // ---- stage feat fp16: warp-per-row, per-row pointer computed once ----
    for (int r = wid; r < 80; r += 8) {
        unsigned* dst = (unsigned*)(feat_s + r * FS);
        if (r < 75) {
            int s = (r >= 50) ? 2 : (r >= 25 ? 1 : 0);
            int w = r - s * 25;
            const unsigned* src = (const unsigned*)
                (g_feat + (size_t)((s * Nn + n) * COUT + o) * VT + w * 300);
            for (int c = lane; c < 156; c += 32)
                dst[c] = (c < 150) ? src[c] : 0u;
        } else {
            for (int c = lane; c < 156; c += 32) dst[c] = 0u;
        }
    }
    // ---- stage A fp16: thread-per-(v, k-phase), incremental s/w ----
    {
        int v = tid >> 3;
        int k0r = tid & 7;
        __half* dstA = A_s + v * 80;
        if (v < 25) {
            const float* base = g_A + (size_t)(n * COUT + o) * VV + v * 25;
            const size_t sStride = (size_t)Nn * COUT * VV;
            int s = 0, w = k0r;
            for (int k = k0r; k < 80; k += 8) {
                float av = 0.f;
                if (k < 75) av = base[(size_t)s * sStride + w];
                dstA[k] = __float2half_rn(av);
                w += 8; if (w >= 25) { w -= 25; s++; }
            }
        } else {
            for (int k = k0r; k < 80; k += 8) dstA[k] = __ushort_as_half((unsigned short)0);
        }
    }
    __syncthreads();

    uint32_t sb = smem_u32(sm);
    int wn0 = wid * 40;

    float acc[2][5][4];
#pragma unroll
    for (int mi = 0; mi < 2; mi++)
#pragma unroll
        for (int ni = 0; ni < 5; ni++)
#pragma unroll
            for (int q = 0; q < 4; q++) acc[mi][ni][q] = 0.f;

#pragma unroll
    for (int k0 = 0; k0 < 80; k0 += 16) {
        uint32_t a[2][4];
#pragma unroll
        for (int mi = 0; mi < 2; mi++) {
            int row = mi * 16 + (lane & 15);
            int col = k0 + (lane >> 4) * 8;
            LDSM_X4(a[mi], sb + KCM_A + (uint32_t)(row * 80 + col) * 2);
        }
        uint32_t b[5][2];
        {
            int krow = k0 + (lane & 15);
            int ncl = ((lane >> 4) << 3);
            uint32_t r4[4];
            LDSM_X4T(r4, sb + (uint32_t)(krow * FS + wn0 + ncl) * 2);
            b[0][0] = r4[0]; b[0][1] = r4[1]; b[1][0] = r4[2]; b[1][1] = r4[3];
            LDSM_X4T(r4, sb + (uint32_t)(krow * FS + wn0 + 16 + ncl) * 2);
            b[2][0] = r4[0]; b[2][1] = r4[1]; b[3][0] = r4[2]; b[3][1] = r4[3];
            LDSM_X2T(b[4], sb + (uint32_t)(krow * FS + wn0 + 32) * 2);
        }
#pragma unroll
        for (int mi = 0; mi < 2; mi++)
#pragma unroll
            for (int ni = 0; ni < 5; ni++)
                MMA_F16(acc[mi][ni], a[mi], b[ni]);
    }

    __syncthreads();

#pragma unroll
    for (int mi = 0; mi < 2; mi++)
#pragma unroll
        for (int ni = 0; ni < 5; ni++) {
            int c = wn0 + ni * 8 + (lane & 3) * 2;
            if (c < 304) {
                int r = mi * 16 + (lane >> 2);
                *(float2*)(Cs + r * CSd + c)       = make_float2(acc[mi][ni][0], acc[mi][ni][1]);
                *(float2*)(Cs + (r + 8) * CSd + c) = make_float2(acc[mi][ni][2], acc[mi][ni][3]);
            }
        }
    __syncthreads();

    float scale = bn_g[o] * rsqrtf(bn_v[o] + EPSf);
    float shift = bn_b[o] - bn_m[o] * scale;
    for (int idx = tid; idx < 25 * 75; idx += 256) {
        int v = idx / 75, t4 = (idx % 75) * 4;
        float4 g = *(float4*)(Cs + v * CSd + t4);
        float* op = out + ((size_t)n * COUT + o) * VT + v * 300 + t4;
        float4 r = *(float4*)op;
        r.x = fmaxf(fmaf(g.x, scale, shift) + r.x, 0.f);
        r.y = fmaxf(fmaf(g.y, scale, shift) + r.y, 0.f);
        r.z = fmaxf(fmaf(g.z, scale, shift) + r.z, 0.f);
        r.w = fmaxf(fmaf(g.w, scale, shift) + r.w, 0.f);
        *(float4*)op = r;
    }
}

// ---------------------------------------------------------------------------
extern "C" void kernel_launch(void* const* d_in, const int* in_sizes, int n_in,
                              void* d_out, int out_size) {
    const float* x       = (const float*)d_in[0];
    const float* ada_A   = (const float*)d_in[1];
    const float* PA      = (const float*)d_in[2];
    const float* conv3_w = (const float*)d_in[3];
    const float* conv3_b = (const float*)d_in[4];
    const float* ada_w   = (const float*)d_in[5];
    const float* ada_b   = (const float*)d_in[6];
    const float* bn_g    = (const float*)d_in[7];
    const float* bn_b    = (const float*)d_in[8];
    const float* bn_m    = (const float*)d_in[9];
    const float* bn_v    = (const float*)d_in[10];
    const float* down_w  = (const float*)d_in[11];
    const float* down_b  = (const float*)d_in[12];
    const float* dbn_g   = (const float*)d_in[13];
    const float* dbn_b   = (const float*)d_in[14];
    const float* dbn_m   = (const float*)d_in[15];
    const float* dbn_v   = (const float*)d_in[16];
    float* out = (float*)d_out;

    cudaFuncSetAttribute(kA,   cudaFuncAttributeMaxDynamicSharedMemorySize, KA_SMEM);
    cudaFuncSetAttribute(kB_m, cudaFuncAttributeMaxDynamicSharedMemorySize, KBM_SMEM);
    cudaFuncSetAttribute(kC_m, cudaFuncAttributeMaxDynamicSharedMemorySize, KCM_SMEM);

    kX<<<(Nn * CIN * VT / 4 + 255) / 256, 256>>>(x);
    kW<<<64, 512>>>(conv3_w, conv3_b, down_w, down_b, dbn_g, dbn_b, dbn_m, dbn_v);
    kA<<<dim3(20, Nn, Ss), 128, KA_SMEM>>>(ada_A, PA, ada_w, ada_b);
    kB_m<<<dim3(59, 4, Nn), 512, KBM_SMEM>>>(out);
    kC_m<<<dim3(COUT, Nn), 256, KCM_SMEM>>>(bn_g, bn_b, bn_m, bn_v, out);
}

// round 12
// speedup vs baseline: 1.3236x; 1.3236x over previous
#include <cuda_runtime.h>
#include <cuda_fp16.h>
#include <cuda_bf16.h>
#include <cstdint>

#define Nn   32
#define CIN  64
#define COUT 128
#define Vv   25
#define Tlen 300
#define Ss   3
#define VT   7500
#define VV   625
#define EPSf 1e-5f
#define FS   312   // padded feat row length (halves)

typedef unsigned long long u64;

// ---- device scratch (allocation-free) ----
// g_feat layout: [n][o][80 rows (s*25+w)][FS cols (t)] fp16, pre-padded tile.
// Rows 75..79 and cols 300..311 are NEVER written -> stay zero (static init).
__device__ __align__(16) __half g_feat[(size_t)Nn * COUT * 80 * FS];  // 204 MB
__device__ __align__(16) float  g_A[Ss * Nn * COUT * VV];             // 30.7 MB
__device__ __align__(16) __half g_Xhi[Nn * CIN * VT];
__device__ __align__(16) __half g_Xlo[Nn * CIN * VT];
__device__ __align__(16) __half g_Whi[512 * 64];
__device__ __align__(16) __half g_Wlo[512 * 64];
__device__ __align__(16) float g_bias[512];

// ---- scalar/FMA2 helpers ----
__device__ __forceinline__ void fma2(u64& d, u64 a, u64 b) {
    asm("fma.rn.f32x2 %0, %1, %2, %0;" : "+l"(d) : "l"(a), "l"(b));
}
__device__ __forceinline__ u64 dup2(float v) {
    u64 r; asm("mov.b64 %0, {%1, %1};" : "=l"(r) : "f"(v)); return r;
}
__device__ __forceinline__ u64 pack2(float lo, float hi) {
    u64 r; asm("mov.b64 %0, {%1, %2};" : "=l"(r) : "f"(lo), "f"(hi)); return r;
}
__device__ __forceinline__ float lo32(u64 v) { return __uint_as_float((unsigned)v); }
__device__ __forceinline__ float hi32(u64 v) { return __uint_as_float((unsigned)(v >> 32)); }

__device__ __forceinline__ uint32_t smem_u32(const void* p) {
    uint32_t a;
    asm("{ .reg .u64 t; cvta.to.shared.u64 t, %1; cvt.u32.u64 %0, t; }" : "=r"(a) : "l"(p));
    return a;
}

// ---- mma.sync / ldmatrix ----
#define LDSM_X4(r, addr) \
    asm volatile("ldmatrix.sync.aligned.m8n8.x4.shared.b16 {%0,%1,%2,%3}, [%4];" \
        : "=r"((r)[0]), "=r"((r)[1]), "=r"((r)[2]), "=r"((r)[3]) : "r"(addr))
#define LDSM_X2T(r, addr) \
    asm volatile("ldmatrix.sync.aligned.m8n8.x2.trans.shared.b16 {%0,%1}, [%2];" \
        : "=r"((r)[0]), "=r"((r)[1]) : "r"(addr))
#define MMA_F16(d, a, b) \
    asm volatile("mma.sync.aligned.m16n8k16.row.col.f32.f16.f16.f32 " \
        "{%0,%1,%2,%3}, {%4,%5,%6,%7}, {%8,%9}, {%0,%1,%2,%3};" \
        : "+f"((d)[0]), "+f"((d)[1]), "+f"((d)[2]), "+f"((d)[3]) \
        : "r"((a)[0]), "r"((a)[1]), "r"((a)[2]), "r"((a)[3]), "r"((b)[0]), "r"((b)[1]))

// ---------------------------------------------------------------------------
// kX: pre-split x (fp32) into fp16 hi/lo, linear layout identical to x.
// ---------------------------------------------------------------------------
__global__ void kX(const float* __restrict__ x) {
    size_t i4 = ((size_t)blockIdx.x * blockDim.x + threadIdx.x) * 4;
    if (i4 >= (size_t)Nn * CIN * VT) return;
    float4 v = *(const float4*)(x + i4);
    __half h0 = __float2half_rn(v.x), h1 = __float2half_rn(v.y);
    __half h2 = __float2half_rn(v.z), h3 = __float2half_rn(v.w);
    __half2 p0(h0, h1), p1(h2, h3);
    uint2 ph; ph.x = *(unsigned*)&p0; ph.y = *(unsigned*)&p1;
    *(uint2*)(g_Xhi + i4) = ph;
    __half2 q0(__float2half_rn(v.x - __half2float(h0)), __float2half_rn(v.y - __half2float(h1)));
    __half2 q1(__float2half_rn(v.z - __half2float(h2)), __float2half_rn(v.w - __half2float(h3)));
    uint2 pl; pl.x = *(unsigned*)&q0; pl.y = *(unsigned*)&q1;
    *(uint2*)(g_Xlo + i4) = pl;
}

// ---------------------------------------------------------------------------
// kW: split folded W into fp16 hi/lo + bias
// ---------------------------------------------------------------------------
__global__ void kW(const float* __restrict__ conv3_w, const float* __restrict__ conv3_b,
                   const float* __restrict__ down_w,  const float* __restrict__ down_b,
                   const float* __restrict__ dg, const float* __restrict__ dbeta,
                   const float* __restrict__ dm, const float* __restrict__ dvar) {
    int idx = blockIdx.x * blockDim.x + threadIdx.x;
    if (idx >= 512 * 64) return;
    int r = idx >> 6, k = idx & 63;
    float w;
    if (r < Ss * COUT) {
        w = conv3_w[r * CIN + k];
    } else {
        int o = r - Ss * COUT;
        w = dg[o] * rsqrtf(dvar[o] + EPSf) * down_w[o * CIN + k];
    }
    __half hi = __float2half_rn(w);
    g_Whi[idx] = hi;
    g_Wlo[idx] = __float2half_rn(w - __half2float(hi));
    if (k == 0) {
        float b;
        if (r < Ss * COUT) b = conv3_b[r];
        else {
            int o = r - Ss * COUT;
            float sc = dg[o] * rsqrtf(dvar[o] + EPSf);
            b = sc * (down_b[o] - dm[o]) + dbeta[o];
        }
        g_bias[r] = b;
    }
}

// ---------------------------------------------------------------------------
// kA: g_A = (ada_w . ada_A + ada_b) * PA. grid (20, n, s), 128 threads, FMA2.
// ---------------------------------------------------------------------------
#define KA_SMEM (64 * 16 * 8 + 64 * 125 * 4 + 32 * 4)
__global__ void __launch_bounds__(128)
kA(const float* __restrict__ adaA, const float* __restrict__ PA,
   const float* __restrict__ ada_w, const float* __restrict__ ada_b) {
    extern __shared__ char smA[];
    u64*   Wp  = (u64*)smA;
    float* Xa  = (float*)(smA + 64 * 16 * 8);
    float* bsm = (float*)(smA + 64 * 16 * 8 + 64 * 125 * 4);

    int tid = threadIdx.x;
    int s = blockIdx.z, n = blockIdx.y;
    int g = blockIdx.x & 3;
    int vw0 = (blockIdx.x >> 2) * 125;

    const float* wsrc = ada_w + s * COUT * CIN + g * 32 * CIN;
    for (int idx = tid; idx < 64 * 16; idx += 128) {
        int i = idx >> 4, op = idx & 15;
        Wp[i * 16 + op] = pack2(wsrc[(2 * op) * CIN + i], wsrc[(2 * op + 1) * CIN + i]);
    }
    for (int idx = tid; idx < 64 * 125; idx += 128) {
        int i = idx / 125, j = idx % 125;
        Xa[i * 125 + j] = adaA[(size_t)(n * CIN + i) * VV + vw0 + j];
    }
    if (tid < 32) bsm[tid] = ada_b[s * COUT + g * 32 + tid];
    __syncthreads();
    if (tid >= 125) return;

    int vw = vw0 + tid;
    float pa = PA[s * VV + vw];

    u64 acc[16];
#pragma unroll
    for (int p = 0; p < 16; p++) acc[p] = 0ull;

#pragma unroll 8
    for (int i = 0; i < CIN; i++) {
        u64 f2 = dup2(Xa[i * 125 + tid]);
        const ulonglong2* wr = (const ulonglong2*)(Wp + i * 16);
#pragma unroll
        for (int p = 0; p < 8; p++) {
            ulonglong2 wv = wr[p];
            fma2(acc[2 * p],     wv.x, f2);
            fma2(acc[2 * p + 1], wv.y, f2);
        }
    }
    float* outp = g_A + ((size_t)((s * Nn + n) * COUT) + g * 32) * VV + vw;
#pragma unroll
    for (int p = 0; p < 16; p++) {
        outp[(size_t)(2 * p) * VV]     = (lo32(acc[p]) + bsm[2 * p])     * pa;
        outp[(size_t)(2 * p + 1) * VV] = (hi32(acc[p]) + bsm[2 * p + 1]) * pa;
    }
}

// ---------------------------------------------------------------------------
// kB_m: tensor GEMM C[128r x 128c] = W[128x64] @ X[64 x 128c].  (R10 mainloop)
// feat rows write to PADDED per-(n,o) tiles: g_feat[((n*128+o)*80 + rg*25+w)*FS + t]
// grid (59, 4, 32), 512 threads, 2 CTAs/SM.
// ---------------------------------------------------------------------------
#define PADK 72
#define PADC 136
#define WHI_OFF 0
#define WLO_OFF (128 * PADK * 2)
#define XHI_OFF (WLO_OFF + 128 * PADK * 2)
#define XLO_OFF (XHI_OFF + 64 * PADC * 2)
#define BIAS_OFF (XLO_OFF + 64 * PADC * 2)
#define KBM_SMEM (BIAS_OFF + 128 * 4)
__global__ void __launch_bounds__(512, 2)
kB_m(float* __restrict__ out) {
    extern __shared__ char sm[];
    __half* Whi_s = (__half*)(sm + WHI_OFF);
    __half* Wlo_s = (__half*)(sm + WLO_OFF);
    __half* Xhi_s = (__half*)(sm + XHI_OFF);
    __half* Xlo_s = (__half*)(sm + XLO_OFF);
    float* bias_s = (float*)(sm + BIAS_OFF);
    float* Cs = (float*)sm;

    int tid = threadIdx.x;
    int wid = tid >> 5, lane = tid & 31;
    int n = blockIdx.z, rg = blockIdx.y;
    int c0 = blockIdx.x * 128;
    int r0 = rg * 128;
    int ncols = VT - c0; if (ncols > 128) ncols = 128;
    bool isRes = (rg == 3);
    // uniform w/t decomposition helpers (tile crosses at most one w boundary)
    int w0 = c0 / 300;
    int rem0 = c0 - w0 * 300;

    for (int idx = tid; idx < 1024; idx += 512) {
        int row = idx >> 3, kc = (idx & 7) * 8;
        uint4 v = *(const uint4*)(g_Whi + (size_t)(r0 + row) * 64 + kc);
        *(uint4*)(Whi_s + row * PADK + kc) = v;
    }
    if (isRes) {
        for (int idx = tid; idx < 1024; idx += 512) {
            int row = idx >> 3, kc = (idx & 7) * 8;
            uint4 v = *(const uint4*)(g_Wlo + (size_t)(r0 + row) * 64 + kc);
            *(uint4*)(Wlo_s + row * PADK + kc) = v;
        }
    }
    if (tid < 128) bias_s[tid] = g_bias[r0 + tid];

    for (int idx = tid; idx < 64 * 32; idx += 512) {
        int k = idx >> 5, c4 = (idx & 31) << 2;
        uint2 v = make_uint2(0u, 0u);
        if (c4 < ncols) v = *(const uint2*)(g_Xhi + (size_t)(n * CIN + k) * VT + c0 + c4);
        *(uint2*)(Xhi_s + k * PADC + c4) = v;
        if (isRes) {
            uint2 vl = make_uint2(0u, 0u);
            if (c4 < ncols) vl = *(const uint2*)(g_Xlo + (size_t)(n * CIN + k) * VT + c0 + c4);
            *(uint2*)(Xlo_s + k * PADC + c4) = vl;
        }
    }
    __syncthreads();

    int wm0 = (wid & 3) * 32;
    int wn0 = (wid >> 2) * 32;
    uint32_t sbase = smem_u32(sm);

    float acc[2][4][4];
#pragma unroll
    for (int mi = 0; mi < 2; mi++)
#pragma unroll
        for (int ni = 0; ni < 4; ni++)
#pragma unroll
            for (int q = 0; q < 4; q++) acc[mi][ni][q] = 0.f;

#pragma unroll
    for (int k0 = 0; k0 < 64; k0 += 16) {
        uint32_t a_hi[2][4], b_hi[4][2];
#pragma unroll
        for (int mi = 0; mi < 2; mi++) {
            int row = wm0 + mi * 16 + (lane & 15);
            int col = k0 + (lane >> 4) * 8;
            LDSM_X4(a_hi[mi], sbase + WHI_OFF + (uint32_t)(row * PADK + col) * 2);
        }
#pragma unroll
        for (int ni = 0; ni < 4; ni++) {
            int krow = k0 + (lane & 15);
            LDSM_X2T(b_hi[ni], sbase + XHI_OFF + (uint32_t)(krow * PADC + wn0 + ni * 8) * 2);
        }
#pragma unroll
        for (int mi = 0; mi < 2; mi++)
#pragma unroll
            for (int ni = 0; ni < 4; ni++)
                MMA_F16(acc[mi][ni], a_hi[mi], b_hi[ni]);

        if (isRes) {
            uint32_t a_lo[2][4], b_lo[4][2];
#pragma unroll
            for (int mi = 0; mi < 2; mi++) {
                int row = wm0 + mi * 16 + (lane & 15);
                int col = k0 + (lane >> 4) * 8;
                LDSM_X4(a_lo[mi], sbase + WLO_OFF + (uint32_t)(row * PADK + col) * 2);
            }
#pragma unroll
            for (int ni = 0; ni < 4; ni++) {
                int krow = k0 + (lane & 15);
                LDSM_X2T(b_lo[ni], sbase + XLO_OFF + (uint32_t)(krow * PADC + wn0 + ni * 8) * 2);
            }
#pragma unroll
            for (int mi = 0; mi < 2; mi++)
#pragma unroll
                for (int ni = 0; ni < 4; ni++) {
                    MMA_F16(acc[mi][ni], a_hi[mi], b_lo[ni]);
                    MMA_F16(acc[mi][ni], a_lo[mi], b_hi[ni]);
                }
        }
    }

    __syncthreads();

#pragma unroll
    for (int mi = 0; mi < 2; mi++)
#pragma unroll
        for (int ni = 0; ni < 4; ni++) {
            int r = wm0 + mi * 16 + (lane >> 2);
            int c = wn0 + ni * 8 + (lane & 3) * 2;
            *(float2*)(Cs + r * 132 + c)       = make_float2(acc[mi][ni][0], acc[mi][ni][1]);
            *(float2*)(Cs + (r + 8) * 132 + c) = make_float2(acc[mi][ni][2], acc[mi][ni][3]);
        }
    __syncthreads();

    for (int idx = tid; idx < 128 * 32; idx += 512) {
        int row = idx >> 5, c = (idx & 31) * 4;
        if (c >= ncols) continue;
        float4 v = *(float4*)(Cs + row * 132 + c);
        float b = bias_s[row];
        v.x += b; v.y += b; v.z += b; v.w += b;
        if (!isRes) {
            __half2 h0 = __floats2half2_rn(v.x, v.y);
            __half2 h1 = __floats2half2_rn(v.z, v.w);
            uint2 pk; pk.x = *(unsigned*)&h0; pk.y = *(unsigned*)&h1;
            int cl = rem0 + c;
            int w = w0, t = cl;
            if (cl >= 300) { w = w0 + 1; t = cl - 300; }
            *(uint2*)(g_feat + ((size_t)(n * COUT + row) * 80 + rg * 25 + w) * FS + t) = pk;
        } else {
            *(float4*)(out + (size_t)(n * COUT + row) * VT + c0 + c) = v;
        }
    }
}

// ---------------------------------------------------------------------------
// kC_m: per (o, n): Out[25 x 300] = A[25 x 75] @ feat[75 x 300] (fp16 mma),
// then bn + residual + relu. feat staging = pure flat uint4 memcpy.
// ---------------------------------------------------------------------------
#define CSd 308
#define KCM_A   (80 * FS * 2)          // 49920
#define KCM_SMEM (KCM_A + 32 * 80 * 2) // 55040
__global__ void __launch_bounds__(256)
kC_m(const float* __restrict__ bn_g, const float* __restrict__ bn_b,
     const float* __restrict__ bn_m, const float* __restrict__ bn_v,
     float* __restrict__ out) {
    extern __shared__ char sm[];
    __half* feat_s = (__half*)sm;           // [80][FS] — exact image of g_feat tile
    __half* A_s    = (__half*)(sm + KCM_A); // [v 32][k 80]
    float*  Cs     = (float*)sm;            // reuse: [32][CSd]

    int tid = threadIdx.x;
    int wid = tid >> 5, lane = tid & 31;
    int o = blockIdx.x, n = blockIdx.y;

    // ---- stage feat: flat uint4 copy (80*FS*2 bytes = 3120 uint4) ----
    {
        const uint4* src = (const uint4*)(g_feat + (size_t)(n * COUT + o) * 80 * FS);
        uint4* dst = (uint4*)feat_s;
        for (int idx = tid; idx < 80 * FS * 2 / 16; idx += 256)
            dst[idx] = src[idx];
    }
    // ---- stage A fp16 (zero-padded to 32 x 80) — R7 version ----
    for (int idx = tid; idx < 32 * 80; idx += 256) {
        int v = idx / 80, k = idx % 80;
        float av = 0.f;
        if (v < 25 && k < 75) {
            int s = k / 25, w = k % 25;
            av = g_A[(size_t)((s * Nn + n) * COUT + o) * VV + v * 25 + w];
        }
        A_s[v * 80 + k] = __float2half_rn(av);
    }
    __syncthreads();

    uint32_t sb = smem_u32(sm);
    int wn0 = wid * 40;

    float acc[2][5][4];
#pragma unroll
    for (int mi = 0; mi < 2; mi++)
#pragma unroll
        for (int ni = 0; ni < 5; ni++)
#pragma unroll
            for (int q = 0; q < 4; q++) acc[mi][ni][q] = 0.f;

#pragma unroll
    for (int k0 = 0; k0 < 80; k0 += 16) {
        uint32_t a[2][4];
#pragma unroll
        for (int mi = 0; mi < 2; mi++) {
            int row = mi * 16 + (lane & 15);
            int col = k0 + (lane >> 4) * 8;
            LDSM_X4(a[mi], sb + KCM_A + (uint32_t)(row * 80 + col) * 2);
        }
        uint32_t b[5][2];
#pragma unroll
        for (int ni = 0; ni < 5; ni++) {
            int krow = k0 + (lane & 15);
            LDSM_X2T(b[ni], sb + (uint32_t)(krow * FS + wn0 + ni * 8) * 2);
        }
#pragma unroll
        for (int mi = 0; mi < 2; mi++)
#pragma unroll
            for (int ni = 0; ni < 5; ni++)
                MMA_F16(acc[mi][ni], a[mi], b[ni]);
    }

    __syncthreads();

#pragma unroll
    for (int mi = 0; mi < 2; mi++)
#pragma unroll
        for (int ni = 0; ni < 5; ni++) {
            int c = wn0 + ni * 8 + (lane & 3) * 2;
            if (c < 304) {
                int r = mi * 16 + (lane >> 2);
                *(float2*)(Cs + r * CSd + c)       = make_float2(acc[mi][ni][0], acc[mi][ni][1]);
                *(float2*)(Cs + (r + 8) * CSd + c) = make_float2(acc[mi][ni][2], acc[mi][ni][3]);
            }
        }
    __syncthreads();

    float scale = bn_g[o] * rsqrtf(bn_v[o] + EPSf);
    float shift = bn_b[o] - bn_m[o] * scale;
    for (int idx = tid; idx < 25 * 75; idx += 256) {
        int v = idx / 75, t4 = (idx % 75) * 4;
        float4 g = *(float4*)(Cs + v * CSd + t4);
        float* op = out + ((size_t)n * COUT + o) * VT + v * 300 + t4;
        float4 r = *(float4*)op;
        r.x = fmaxf(fmaf(g.x, scale, shift) + r.x, 0.f);
        r.y = fmaxf(fmaf(g.y, scale, shift) + r.y, 0.f);
        r.z = fmaxf(fmaf(g.z, scale, shift) + r.z, 0.f);
        r.w = fmaxf(fmaf(g.w, scale, shift) + r.w, 0.f);
        *(float4*)op = r;
    }
}

// ---------------------------------------------------------------------------
extern "C" void kernel_launch(void* const* d_in, const int* in_sizes, int n_in,
                              void* d_out, int out_size) {
    const float* x       = (const float*)d_in[0];
    const float* ada_A   = (const float*)d_in[1];
    const float* PA      = (const float*)d_in[2];
    const float* conv3_w = (const float*)d_in[3];
    const float* conv3_b = (const float*)d_in[4];
    const float* ada_w   = (const float*)d_in[5];
    const float* ada_b   = (const float*)d_in[6];
    const float* bn_g    = (const float*)d_in[7];
    const float* bn_b    = (const float*)d_in[8];
    const float* bn_m    = (const float*)d_in[9];
    const float* bn_v    = (const float*)d_in[10];
    const float* down_w  = (const float*)d_in[11];
    const float* down_b  = (const float*)d_in[12];
    const float* dbn_g   = (const float*)d_in[13];
    const float* dbn_b   = (const float*)d_in[14];
    const float* dbn_m   = (const float*)d_in[15];
    const float* dbn_v   = (const float*)d_in[16];
    float* out = (float*)d_out;

    cudaFuncSetAttribute(kA,   cudaFuncAttributeMaxDynamicSharedMemorySize, KA_SMEM);
    cudaFuncSetAttribute(kB_m, cudaFuncAttributeMaxDynamicSharedMemorySize, KBM_SMEM);
    cudaFuncSetAttribute(kC_m, cudaFuncAttributeMaxDynamicSharedMemorySize, KCM_SMEM);

    kX<<<(Nn * CIN * VT / 4 + 255) / 256, 256>>>(x);
    kW<<<64, 512>>>(conv3_w, conv3_b, down_w, down_b, dbn_g, dbn_b, dbn_m, dbn_v);
    kA<<<dim3(20, Nn, Ss), 128, KA_SMEM>>>(ada_A, PA, ada_w, ada_b);
    kB_m<<<dim3(59, 4, Nn), 512, KBM_SMEM>>>(out);
    kC_m<<<dim3(COUT, Nn), 256, KCM_SMEM>>>(bn_g, bn_b, bn_m, bn_v, out);
}